// round 8
// baseline (speedup 1.0000x reference)
#include <cuda_runtime.h>
#include <cuda_bf16.h>
#include <cstdint>

typedef unsigned long long ull;

#define HARD_CUT 6.5f
#define PI_F 3.14159265358979f

#define KTOT 1728            // 1600 scalar + 80 self + 48 zero pad (27*64)
#define KCH  64
#define NCH  27
#define MPAD 20096           // 157*128

// smem stage layout (bytes, per buffer)
#define OFF_AH 0
#define OFF_AL 16384
#define OFF_BH 32768
#define OFF_BL 43008
#define STG_BYTES 53248

// ---------------- scratch (static __device__, zero-init => pad rows/cols stay 0) ----
__device__ __align__(16) __nv_bfloat16 g_env_hi[(size_t)MPAD * KTOT];
__device__ __align__(16) __nv_bfloat16 g_env_lo[(size_t)MPAD * KTOT];
__device__ __align__(16) __nv_bfloat16 g_w2h[80 * KTOT];   // B[N=80][K] K-major
__device__ __align__(16) __nv_bfloat16 g_w2l[80 * KTOT];

// exp(-0.5*delta^2) for delta = 0..19 (values < 1e-37 flushed to 0)
__constant__ float c_kt[20] = {
    1.0f, 0.60653066f, 0.13533528f, 1.1108997e-2f, 3.3546263e-4f,
    3.7266532e-6f, 1.5229980e-8f, 2.2897348e-11f, 1.2664166e-14f,
    2.5767306e-18f, 1.9287498e-22f, 5.3110924e-27f, 5.3801861e-32f,
    0.0f, 0.0f, 0.0f, 0.0f, 0.0f, 0.0f, 0.0f };

// ---------------- helpers ----------------
__device__ __forceinline__ void ffma2(ull &d, ull a, ull b) {
    asm("fma.rn.f32x2 %0, %1, %2, %0;" : "+l"(d) : "l"(a), "l"(b));
}
__device__ __forceinline__ ull dup2(float v) {
    ull d; asm("mov.b64 %0, {%1, %1};" : "=l"(d) : "r"(__float_as_uint(v))); return d;
}
__device__ __forceinline__ float2 unpack2(ull v) {
    return make_float2(__uint_as_float((unsigned)(v & 0xffffffffull)),
                       __uint_as_float((unsigned)(v >> 32)));
}
__device__ __forceinline__ int lower_bound_i(const int* __restrict__ arr, int n, int val) {
    int lo = 0, hi = n;
    while (lo < hi) { int mid = (lo + hi) >> 1; if (arr[mid] < val) lo = mid + 1; else hi = mid; }
    return lo;
}
__device__ __forceinline__ uint32_t smem_u32(const void* p) {
    uint32_t a;
    asm("{ .reg .u64 t; cvta.to.shared.u64 t, %1; cvt.u32.u64 %0, t; }" : "=r"(a) : "l"(p));
    return a;
}
__device__ __forceinline__ void ldsm4(unsigned* r, uint32_t addr) {
    asm volatile("ldmatrix.sync.aligned.m8n8.x4.shared.b16 {%0,%1,%2,%3}, [%4];"
        : "=r"(r[0]), "=r"(r[1]), "=r"(r[2]), "=r"(r[3]) : "r"(addr));
}
__device__ __forceinline__ void ldsm2(unsigned* r, uint32_t addr) {
    asm volatile("ldmatrix.sync.aligned.m8n8.x2.shared.b16 {%0,%1}, [%2];"
        : "=r"(r[0]), "=r"(r[1]) : "r"(addr));
}
__device__ __forceinline__ void mma16816(float* d, const unsigned* a, const unsigned* b) {
    asm volatile("mma.sync.aligned.m16n8k16.row.col.f32.bf16.bf16.f32 "
        "{%0,%1,%2,%3}, {%4,%5,%6,%7}, {%8,%9}, {%0,%1,%2,%3};"
        : "+f"(d[0]), "+f"(d[1]), "+f"(d[2]), "+f"(d[3])
        : "r"(a[0]), "r"(a[1]), "r"(a[2]), "r"(a[3]), "r"(b[0]), "r"(b[1]));
}
#define CP16(dst, src)  asm volatile("cp.async.cg.shared.global [%0], [%1], 16;" :: "r"(dst), "l"(src) : "memory")
#define CP_COMMIT()     asm volatile("cp.async.commit_group;" ::: "memory")
#define CP_WAIT1()      asm volatile("cp.async.wait_group 1;" ::: "memory")
#define CP_WAIT0()      asm volatile("cp.async.wait_group 0;" ::: "memory")

// ---------------- K0: W2 -> bf16 hi/lo, [80 o][1728 k] K-major ----------------
__global__ void build_w_kernel(const float* __restrict__ iw, const float* __restrict__ selfw) {
    int idx = blockIdx.x * blockDim.x + threadIdx.x;
    if (idx >= 80 * KTOT) return;
    int o = idx / KTOT, k = idx % KTOT;
    float v = 0.0f;
    if (k < 1600)      { int s = k / 80, f = k % 80; v = iw[s * 6400 + o * 80 + f]; }
    else if (k < 1680) { v = selfw[o * 80 + (k - 1600)]; }
    __nv_bfloat16 h = __float2bfloat16(v);
    __nv_bfloat16 l = __float2bfloat16(v - __bfloat162float(h));
    g_w2h[idx] = h;
    g_w2l[idx] = l;
}

// ---------------- K1: segmented envsum -> bf16 hi/lo env ----------------
// Block per atom, 320 threads, 16-pair chunks. One lane per pair computes all
// 20 senses via the factored-Gaussian chain (5 MUFU/pair). Consumer: 2cs x 10f
// register tile, f32x2 FMA; channel weight applied in-consumer.
__global__ __launch_bounds__(320) void envsum_kernel(
    const float* __restrict__ feat, const float* __restrict__ dist,
    const float* __restrict__ coord, const float* __restrict__ mu,
    const float* __restrict__ sigma, const int* __restrict__ pf,
    const int* __restrict__ ps, int n_pairs)
{
    __shared__ float s_sense[16][20];
    __shared__ float s_w[16][4];
    __shared__ __align__(16) float s_feat[16][80];

    int a   = blockIdx.x;
    int tid = threadIdx.x;
    int start = lower_bound_i(pf, n_pairs, a);
    int end   = lower_bound_i(pf, n_pairs, a + 1);

    int csg = tid >> 3;  int cs0 = csg * 2;
    int fg  = tid & 7;   int f0  = fg * 10;
    int ci  = cs0 / 20;  int s0i = cs0 % 20;   // both cs in same channel (cs0, 20 even)

    int pp = tid / 20;
    int j  = tid - pp * 20;

    float mu0 = mu[0];
    float is  = 1.0f / sigma[0];

    ull acc[2][5];
    #pragma unroll
    for (int i = 0; i < 2; i++)
        #pragma unroll
        for (int u = 0; u < 5; u++) acc[i][u] = 0ull;

    int nchunk = (end - start + 15) >> 4;

    float nd = 1.0f, nx = 0.f, ny = 0.f, nz = 0.f;
    float4 nf = make_float4(0.f, 0.f, 0.f, 0.f);
    int have = 0;
    if (nchunk > 0 && pp < min(16, end - start)) {
        int p = start + pp;
        if (j == 0) { nd = dist[p]; nx = coord[3 * p]; ny = coord[3 * p + 1]; nz = coord[3 * p + 2]; }
        int r = ps[p]; nf = ((const float4*)feat)[r * 20 + j];
        have = 1;
    }

    for (int ch = 0; ch < nchunk; ch++) {
        __syncthreads();
        if (have) {
            if (j == 0) {
                float d   = nd;
                float inv = 1.0f / d;
                float cut = (d < HARD_CUT) ? 0.5f * (__cosf(PI_F * d * (1.0f / HARD_CUT)) + 1.0f) : 0.0f;
                float t  = (inv - mu0) * is;
                int   js = __float2int_rn(t);
                js = max(0, min(19, js));
                float r  = t - (float)js;
                float E0 = __expf(-0.5f * r * r) * cut;
                float F  = __expf(r);
                float Fi = __expf(-r);
                s_sense[pp][js] = E0;
                float g = E0;
                for (int q = js + 1; q < 20; q++) { g *= F;  s_sense[pp][q] = g * c_kt[q - js]; }
                g = E0;
                for (int q = js - 1; q >= 0; q--) { g *= Fi; s_sense[pp][q] = g * c_kt[js - q]; }
                *(float4*)&s_w[pp][0] = make_float4(1.0f, nx * inv, ny * inv, nz * inv);
            }
            *(float4*)&s_feat[pp][j * 4] = nf;
        }
        int cnt = min(16, end - (start + ch * 16));
        __syncthreads();

        have = 0;
        if (ch + 1 < nchunk) {
            int p0 = start + (ch + 1) * 16;
            if (pp < min(16, end - p0)) {
                int p = p0 + pp;
                if (j == 0) { nd = dist[p]; nx = coord[3 * p]; ny = coord[3 * p + 1]; nz = coord[3 * p + 2]; }
                int r = ps[p]; nf = ((const float4*)feat)[r * 20 + j];
                have = 1;
            }
        }

        #pragma unroll 4
        for (int p = 0; p < cnt; p++) {
            float2 sn = *(const float2*)&s_sense[p][s0i];
            float  wc = s_w[p][ci];
            ull c0d = dup2(sn.x * wc);
            ull c1d = dup2(sn.y * wc);
            #pragma unroll
            for (int u = 0; u < 5; u++) {
                ull fv = *(const ull*)&s_feat[p][f0 + 2 * u];
                ffma2(acc[0][u], c0d, fv);
                ffma2(acc[1][u], c1d, fv);
            }
        }
    }

    int c  = cs0 / 20;
    int s0 = cs0 % 20;
    size_t rbase = (size_t)(a * 4 + c) * KTOT;
    #pragma unroll
    for (int i = 0; i < 2; i++) {
        size_t cb = rbase + (s0 + i) * 80 + f0;
        #pragma unroll
        for (int u = 0; u < 5; u++) {
            float2 v = unpack2(acc[i][u]);
            __nv_bfloat16 h0 = __float2bfloat16(v.x);
            __nv_bfloat16 l0 = __float2bfloat16(v.x - __bfloat162float(h0));
            __nv_bfloat16 h1 = __float2bfloat16(v.y);
            __nv_bfloat16 l1 = __float2bfloat16(v.y - __bfloat162float(h1));
            __nv_bfloat162 hh; hh.x = h0; hh.y = h1;
            __nv_bfloat162 ll; ll.x = l0; ll.y = l1;
            *(__nv_bfloat162*)&g_env_hi[cb + 2 * u] = hh;
            *(__nv_bfloat162*)&g_env_lo[cb + 2 * u] = ll;
        }
    }

    {
        int c2 = tid / 80;   // 0..3
        int f  = tid % 80;
        float v = (c2 == 0) ? feat[a * 80 + f] : 0.0f;
        __nv_bfloat16 h = __float2bfloat16(v);
        __nv_bfloat16 l = __float2bfloat16(v - __bfloat162float(h));
        size_t off = (size_t)(a * 4 + c2) * KTOT + 1600 + f;
        g_env_hi[off] = h;
        g_env_lo[off] = l;
    }
}

// ---------------- K2: bf16-split GEMM via mma.sync + fused epilogue ----------------
// 256 threads = 8 warps: warp (wid>>1) owns 32 M-rows, (wid&1) owns 40 N-cols.
// Stage: A_hi 16K | A_lo 16K | B_hi 10K | B_lo 10K (XOR-swizzled 16B segs), x2 buffers.
__device__ __forceinline__ void load_stage(uint32_t sstage, int m0, int kc, int tid) {
    #pragma unroll
    for (int i = 0; i < 4; i++) {
        int u = tid + i * 256;                 // 1024: 128 rows x 8 segs
        int r = u >> 3, sg = u & 7;
        uint32_t so = (uint32_t)(r * 128 + ((sg ^ (r & 7)) * 16));
        const char* gh = (const char*)(g_env_hi + (size_t)(m0 + r) * KTOT + kc) + sg * 16;
        const char* gl = (const char*)(g_env_lo + (size_t)(m0 + r) * KTOT + kc) + sg * 16;
        CP16(sstage + OFF_AH + so, gh);
        CP16(sstage + OFF_AL + so, gl);
    }
    #pragma unroll
    for (int i = 0; i < 3; i++) {
        int u = tid + i * 256;                 // 640: 80 rows x 8 segs
        if (u < 640) {
            int r = u >> 3, sg = u & 7;
            uint32_t so = (uint32_t)(r * 128 + ((sg ^ (r & 7)) * 16));
            const char* gh = (const char*)(g_w2h + (size_t)r * KTOT + kc) + sg * 16;
            const char* gl = (const char*)(g_w2l + (size_t)r * KTOT + kc) + sg * 16;
            CP16(sstage + OFF_BH + so, gh);
            CP16(sstage + OFF_BL + so, gl);
        }
    }
}

__global__ __launch_bounds__(256, 1)
void gemm_kernel(const float* __restrict__ selfb, const float* __restrict__ vecs,
                 float* __restrict__ out, int n_atoms)
{
    extern __shared__ __align__(1024) char smem[];
    uint32_t sb = smem_u32(smem);
    int tid  = threadIdx.x;
    int lane = tid & 31;
    int wid  = tid >> 5;
    int m0   = blockIdx.x * 128;
    int m0w  = (wid >> 1) * 32;
    int n0w  = (wid & 1) * 40;

    int rA_loc = (lane & 7) + ((lane >> 3) & 1) * 8;
    uint32_t rowA0 = (uint32_t)((m0w + rA_loc) * 128);
    uint32_t rowA1 = rowA0 + 16 * 128;
    int rB_loc = (lane & 7) + ((lane >> 4) & 1) * 8;
    uint32_t rowB0 = (uint32_t)((n0w + rB_loc) * 128);
    uint32_t rowB1 = rowB0 + 16 * 128;
    uint32_t rowB2 = (uint32_t)((n0w + 32 + (lane & 7)) * 128);

    float acc[2][5][4];
    #pragma unroll
    for (int mt = 0; mt < 2; mt++)
        #pragma unroll
        for (int nt = 0; nt < 5; nt++)
            #pragma unroll
            for (int q = 0; q < 4; q++) acc[mt][nt][q] = 0.0f;

    load_stage(sb, m0, 0, tid);              CP_COMMIT();
    load_stage(sb + STG_BYTES, m0, KCH, tid); CP_COMMIT();

    for (int c = 0; c < NCH; c++) {
        if (c < NCH - 1) CP_WAIT1(); else CP_WAIT0();
        __syncthreads();

        uint32_t st  = sb + (uint32_t)((c & 1) * STG_BYTES);
        uint32_t sAH = st + OFF_AH, sAL = st + OFF_AL;
        uint32_t sBH = st + OFF_BH, sBL = st + OFF_BL;

        #pragma unroll
        for (int ks = 0; ks < 4; ks++) {
            uint32_t swA = (uint32_t)((((ks * 2) + (lane >> 4)) ^ (lane & 7)) * 16);
            uint32_t swB = (uint32_t)((((ks * 2) + ((lane >> 3) & 1)) ^ (lane & 7)) * 16);
            unsigned aH[2][4], aL[2][4], bH[10], bL[10];
            ldsm4(aH[0], sAH + rowA0 + swA);
            ldsm4(aH[1], sAH + rowA1 + swA);
            ldsm4(aL[0], sAL + rowA0 + swA);
            ldsm4(aL[1], sAL + rowA1 + swA);
            ldsm4(bH + 0, sBH + rowB0 + swB);
            ldsm4(bH + 4, sBH + rowB1 + swB);
            ldsm2(bH + 8, sBH + rowB2 + swB);
            ldsm4(bL + 0, sBL + rowB0 + swB);
            ldsm4(bL + 4, sBL + rowB1 + swB);
            ldsm2(bL + 8, sBL + rowB2 + swB);
            #pragma unroll
            for (int mt = 0; mt < 2; mt++)
                #pragma unroll
                for (int nt = 0; nt < 5; nt++) {
                    mma16816(acc[mt][nt], aH[mt], bH + 2 * nt);
                    mma16816(acc[mt][nt], aL[mt], bH + 2 * nt);
                    mma16816(acc[mt][nt], aH[mt], bL + 2 * nt);
                }
        }
        __syncthreads();
        if (c + 2 < NCH) { load_stage(sb + (uint32_t)((c & 1) * STG_BYTES), m0, (c + 2) * KCH, tid); CP_COMMIT(); }
    }

    // write accumulators to smem C[128][80]
    float* C = (float*)smem;
    int grp  = lane >> 2;
    int col0 = (lane & 3) * 2;
    #pragma unroll
    for (int mt = 0; mt < 2; mt++) {
        int r0 = m0w + mt * 16 + grp;
        #pragma unroll
        for (int nt = 0; nt < 5; nt++) {
            int cc = n0w + nt * 8 + col0;
            *(float2*)&C[r0 * 80 + cc]       = make_float2(acc[mt][nt][0], acc[mt][nt][1]);
            *(float2*)&C[(r0 + 8) * 80 + cc] = make_float2(acc[mt][nt][2], acc[mt][nt][3]);
        }
    }
    __syncthreads();

    #pragma unroll
    for (int u = tid; u < 2560; u += 256) {
        int al = u / 80, o = u % 80;
        int a = (m0 >> 2) + al;
        if (a < n_atoms) {
            float s0 = C[(al * 4 + 0) * 80 + o];
            float x  = C[(al * 4 + 1) * 80 + o];
            float y  = C[(al * 4 + 2) * 80 + o];
            float z  = C[(al * 4 + 3) * 80 + o];
            out[a * 80 + o] = s0 + selfb[o]
                + vecs[o] * sqrtf(fmaf(x, x, fmaf(y, y, z * z)) + 1e-30f);
        }
    }
}

// ---------------- launch ----------------
extern "C" void kernel_launch(void* const* d_in, const int* in_sizes, int n_in,
                              void* d_out, int out_size) {
    const float* feat  = (const float*)d_in[0];
    const float* dist  = (const float*)d_in[1];
    const float* coord = (const float*)d_in[2];
    const float* iw    = (const float*)d_in[3];
    const float* selfw = (const float*)d_in[4];
    const float* selfb = (const float*)d_in[5];
    const float* vecs  = (const float*)d_in[6];
    const float* mu    = (const float*)d_in[7];
    const float* sigma = (const float*)d_in[8];
    const int*   pf    = (const int*)d_in[9];
    const int*   ps    = (const int*)d_in[10];
    int n_pairs = in_sizes[9];
    int n_atoms = in_sizes[0] / 80;
    float* out = (float*)d_out;

    static int smem_set = 0;
    if (!smem_set) {
        cudaFuncSetAttribute(gemm_kernel, cudaFuncAttributeMaxDynamicSharedMemorySize,
                             2 * STG_BYTES);
        smem_set = 1;
    }

    build_w_kernel<<<(80 * KTOT + 255) / 256, 256>>>(iw, selfw);
    envsum_kernel<<<n_atoms, 320>>>(feat, dist, coord, mu, sigma, pf, ps, n_pairs);
    int mtiles = (n_atoms * 4 + 127) / 128;
    gemm_kernel<<<mtiles, 256, 2 * STG_BYTES>>>(selfb, vecs, out, n_atoms);
}

// round 9
// speedup vs baseline: 1.2116x; 1.2116x over previous
#include <cuda_runtime.h>
#include <cuda_bf16.h>
#include <cstdint>

typedef unsigned long long ull;

#define HARD_CUT 6.5f
#define PI_F 3.14159265358979f

#define KTOT 1728            // 1600 scalar + 80 self + 48 zero pad (27*64)
#define KCH  64
#define NCH  27
#define MPAD 20096           // 157*128
#define ATOMS_PER_BLK 4

// smem stage layout (bytes, per buffer)
#define OFF_AH 0
#define OFF_AL 16384
#define OFF_BH 32768
#define OFF_BL 43008
#define STG_BYTES 53248

// ---------------- scratch (static __device__, zero-init => pad rows/cols stay 0) ----
__device__ __align__(16) __nv_bfloat16 g_env_hi[(size_t)MPAD * KTOT];
__device__ __align__(16) __nv_bfloat16 g_env_lo[(size_t)MPAD * KTOT];
__device__ __align__(16) __nv_bfloat16 g_w2h[80 * KTOT];   // B[N=80][K] K-major
__device__ __align__(16) __nv_bfloat16 g_w2l[80 * KTOT];
__device__ int g_seg[5008];                                // segment starts per atom

// ---------------- helpers ----------------
__device__ __forceinline__ void ffma2(ull &d, ull a, ull b) {
    asm("fma.rn.f32x2 %0, %1, %2, %0;" : "+l"(d) : "l"(a), "l"(b));
}
__device__ __forceinline__ ull dup2(float v) {
    ull d; asm("mov.b64 %0, {%1, %1};" : "=l"(d) : "r"(__float_as_uint(v))); return d;
}
__device__ __forceinline__ float2 unpack2(ull v) {
    return make_float2(__uint_as_float((unsigned)(v & 0xffffffffull)),
                       __uint_as_float((unsigned)(v >> 32)));
}
__device__ __forceinline__ int lower_bound_i(const int* __restrict__ arr, int n, int val) {
    int lo = 0, hi = n;
    while (lo < hi) { int mid = (lo + hi) >> 1; if (arr[mid] < val) lo = mid + 1; else hi = mid; }
    return lo;
}
__device__ __forceinline__ uint32_t smem_u32(const void* p) {
    uint32_t a;
    asm("{ .reg .u64 t; cvta.to.shared.u64 t, %1; cvt.u32.u64 %0, t; }" : "=r"(a) : "l"(p));
    return a;
}
__device__ __forceinline__ void ldsm4(unsigned* r, uint32_t addr) {
    asm volatile("ldmatrix.sync.aligned.m8n8.x4.shared.b16 {%0,%1,%2,%3}, [%4];"
        : "=r"(r[0]), "=r"(r[1]), "=r"(r[2]), "=r"(r[3]) : "r"(addr));
}
__device__ __forceinline__ void ldsm2(unsigned* r, uint32_t addr) {
    asm volatile("ldmatrix.sync.aligned.m8n8.x2.shared.b16 {%0,%1}, [%2];"
        : "=r"(r[0]), "=r"(r[1]) : "r"(addr));
}
__device__ __forceinline__ void mma16816(float* d, const unsigned* a, const unsigned* b) {
    asm volatile("mma.sync.aligned.m16n8k16.row.col.f32.bf16.bf16.f32 "
        "{%0,%1,%2,%3}, {%4,%5,%6,%7}, {%8,%9}, {%0,%1,%2,%3};"
        : "+f"(d[0]), "+f"(d[1]), "+f"(d[2]), "+f"(d[3])
        : "r"(a[0]), "r"(a[1]), "r"(a[2]), "r"(a[3]), "r"(b[0]), "r"(b[1]));
}
#define CP16(dst, src)  asm volatile("cp.async.cg.shared.global [%0], [%1], 16;" :: "r"(dst), "l"(src) : "memory")
#define CP_COMMIT()     asm volatile("cp.async.commit_group;" ::: "memory")
#define CP_WAIT1()      asm volatile("cp.async.wait_group 1;" ::: "memory")
#define CP_WAIT0()      asm volatile("cp.async.wait_group 0;" ::: "memory")

// ---------------- K0a: W2 -> bf16 hi/lo, [80 o][1728 k] K-major ----------------
__global__ void build_w_kernel(const float* __restrict__ iw, const float* __restrict__ selfw) {
    int idx = blockIdx.x * blockDim.x + threadIdx.x;
    if (idx >= 80 * KTOT) return;
    int o = idx / KTOT, k = idx % KTOT;
    float v = 0.0f;
    if (k < 1600)      { int s = k / 80, f = k % 80; v = iw[s * 6400 + o * 80 + f]; }
    else if (k < 1680) { v = selfw[o * 80 + (k - 1600)]; }
    __nv_bfloat16 h = __float2bfloat16(v);
    __nv_bfloat16 l = __float2bfloat16(v - __bfloat162float(h));
    g_w2h[idx] = h;
    g_w2l[idx] = l;
}

// ---------------- K0b: segment boundaries (one binary search per atom) ----------------
__global__ void seg_kernel(const int* __restrict__ pf, int n_pairs, int n_atoms) {
    int a = blockIdx.x * blockDim.x + threadIdx.x;
    if (a <= n_atoms) g_seg[a] = lower_bound_i(pf, n_pairs, a);
}

// ---------------- K1: segmented envsum -> bf16 hi/lo env ----------------
// 4 atoms per block, 320 threads, global 16-pair chunks over the block's pair
// range; consumer flushes accumulators at (uniform) atom boundaries.
// Producer: 20 lanes/pair, each 1 rcp+cos+exp. Consumer: 2cs x 10f f32x2 tile.
__device__ __forceinline__ void flush_acc(ull acc[2][5], int a, int cs0, int f0) {
    int c  = cs0 / 20;
    int s0 = cs0 % 20;
    size_t rbase = (size_t)(a * 4 + c) * KTOT;
    #pragma unroll
    for (int i = 0; i < 2; i++) {
        size_t cb = rbase + (s0 + i) * 80 + f0;
        #pragma unroll
        for (int u = 0; u < 5; u++) {
            float2 v = unpack2(acc[i][u]);
            __nv_bfloat16 h0 = __float2bfloat16(v.x);
            __nv_bfloat16 l0 = __float2bfloat16(v.x - __bfloat162float(h0));
            __nv_bfloat16 h1 = __float2bfloat16(v.y);
            __nv_bfloat16 l1 = __float2bfloat16(v.y - __bfloat162float(h1));
            __nv_bfloat162 hh; hh.x = h0; hh.y = h1;
            __nv_bfloat162 ll; ll.x = l0; ll.y = l1;
            *(__nv_bfloat162*)&g_env_hi[cb + 2 * u] = hh;
            *(__nv_bfloat162*)&g_env_lo[cb + 2 * u] = ll;
            acc[i][u] = 0ull;
        }
    }
}

__global__ __launch_bounds__(320) void envsum_kernel(
    const float* __restrict__ feat, const float* __restrict__ dist,
    const float* __restrict__ coord, const float* __restrict__ mu,
    const float* __restrict__ sigma, const int* __restrict__ ps)
{
    __shared__ __align__(16) float s_coef[16][80];
    __shared__ __align__(16) float s_feat[16][80];

    int a0  = blockIdx.x * ATOMS_PER_BLK;
    int tid = threadIdx.x;

    int segs[ATOMS_PER_BLK + 1];
    #pragma unroll
    for (int i = 0; i <= ATOMS_PER_BLK; i++) segs[i] = g_seg[a0 + i];
    int start  = segs[0];
    int endall = segs[ATOMS_PER_BLK];

    int csg = tid >> 3;  int cs0 = csg * 2;
    int fg  = tid & 7;   int f0  = fg * 10;

    int pp = tid / 20;
    int j  = tid - pp * 20;
    float muj = mu[j];
    float isj = 1.0f / sigma[j];

    ull acc[2][5];
    #pragma unroll
    for (int i = 0; i < 2; i++)
        #pragma unroll
        for (int u = 0; u < 5; u++) acc[i][u] = 0ull;

    int nchunk = (endall - start + 15) >> 4;

    // register prefetch buffers (R5 pattern, now over the global pair range)
    float nd = 1.0f, nx = 0.f, ny = 0.f, nz = 0.f;
    float4 nf = make_float4(0.f, 0.f, 0.f, 0.f);
    int have = 0;
    if (nchunk > 0 && start + pp < endall) {
        int p = start + pp;
        nd = dist[p]; nx = coord[3 * p]; ny = coord[3 * p + 1]; nz = coord[3 * p + 2];
        int r = ps[p]; nf = ((const float4*)feat)[r * 20 + j];
        have = 1;
    }

    int a_cur = a0;
    int bnd   = segs[1];

    for (int ch = 0; ch < nchunk; ch++) {
        __syncthreads();
        if (have) {
            float d   = nd;
            float inv = 1.0f / d;
            float cut = (d < HARD_CUT) ? 0.5f * (__cosf(PI_F * d * (1.0f / HARD_CUT)) + 1.0f) : 0.0f;
            float z   = (inv - muj) * isj;
            float e   = __expf(-0.5f * z * z) * cut;
            s_coef[pp][j]      = e;
            s_coef[pp][20 + j] = e * nx * inv;
            s_coef[pp][40 + j] = e * ny * inv;
            s_coef[pp][60 + j] = e * nz * inv;
            *(float4*)&s_feat[pp][j * 4] = nf;
        }
        int p0  = start + ch * 16;
        int cnt = min(16, endall - p0);
        __syncthreads();

        have = 0;
        if (ch + 1 < nchunk) {
            int p = start + (ch + 1) * 16 + pp;
            if (p < endall) {
                nd = dist[p]; nx = coord[3 * p]; ny = coord[3 * p + 1]; nz = coord[3 * p + 2];
                int r = ps[p]; nf = ((const float4*)feat)[r * 20 + j];
                have = 1;
            }
        }

        for (int p = 0; p < cnt; p++) {
            int gp = p0 + p;
            while (gp == bnd && a_cur < a0 + ATOMS_PER_BLK - 1) {
                flush_acc(acc, a_cur, cs0, f0);
                a_cur++;
                bnd = segs[a_cur - a0 + 1];
            }
            float2 cf = *(const float2*)&s_coef[p][cs0];
            ull c0d = dup2(cf.x);
            ull c1d = dup2(cf.y);
            #pragma unroll
            for (int u = 0; u < 5; u++) {
                ull fv = *(const ull*)&s_feat[p][f0 + 2 * u];
                ffma2(acc[0][u], c0d, fv);
                ffma2(acc[1][u], c1d, fv);
            }
        }
    }

    // flush remaining atoms (covers empty trailing segments too)
    for (int a = a_cur; a < a0 + ATOMS_PER_BLK; a++)
        flush_acc(acc, a, cs0, f0);

    // self-interaction rows for all 4 atoms: env[(a,c), 1600+f] = (c==0) ? feat[a,f] : 0
    {
        int c2 = tid / 80;   // 0..3
        int f  = tid % 80;
        #pragma unroll
        for (int ai = 0; ai < ATOMS_PER_BLK; ai++) {
            int a = a0 + ai;
            float v = (c2 == 0) ? feat[a * 80 + f] : 0.0f;
            __nv_bfloat16 h = __float2bfloat16(v);
            __nv_bfloat16 l = __float2bfloat16(v - __bfloat162float(h));
            size_t off = (size_t)(a * 4 + c2) * KTOT + 1600 + f;
            g_env_hi[off] = h;
            g_env_lo[off] = l;
        }
    }
}

// ---------------- K2: bf16-split GEMM via mma.sync + fused epilogue ----------------
// 256 threads = 8 warps: warp (wid>>1) owns 32 M-rows, (wid&1) owns 40 N-cols.
// Stage: A_hi 16K | A_lo 16K | B_hi 10K | B_lo 10K (XOR-swizzled 16B segs), x2 buffers.
__device__ __forceinline__ void load_stage(uint32_t sstage, int m0, int kc, int tid) {
    #pragma unroll
    for (int i = 0; i < 4; i++) {
        int u = tid + i * 256;                 // 1024: 128 rows x 8 segs
        int r = u >> 3, sg = u & 7;
        uint32_t so = (uint32_t)(r * 128 + ((sg ^ (r & 7)) * 16));
        const char* gh = (const char*)(g_env_hi + (size_t)(m0 + r) * KTOT + kc) + sg * 16;
        const char* gl = (const char*)(g_env_lo + (size_t)(m0 + r) * KTOT + kc) + sg * 16;
        CP16(sstage + OFF_AH + so, gh);
        CP16(sstage + OFF_AL + so, gl);
    }
    #pragma unroll
    for (int i = 0; i < 3; i++) {
        int u = tid + i * 256;                 // 640: 80 rows x 8 segs
        if (u < 640) {
            int r = u >> 3, sg = u & 7;
            uint32_t so = (uint32_t)(r * 128 + ((sg ^ (r & 7)) * 16));
            const char* gh = (const char*)(g_w2h + (size_t)r * KTOT + kc) + sg * 16;
            const char* gl = (const char*)(g_w2l + (size_t)r * KTOT + kc) + sg * 16;
            CP16(sstage + OFF_BH + so, gh);
            CP16(sstage + OFF_BL + so, gl);
        }
    }
}

__global__ __launch_bounds__(256, 1)
void gemm_kernel(const float* __restrict__ selfb, const float* __restrict__ vecs,
                 float* __restrict__ out, int n_atoms)
{
    extern __shared__ __align__(1024) char smem[];
    uint32_t sb = smem_u32(smem);
    int tid  = threadIdx.x;
    int lane = tid & 31;
    int wid  = tid >> 5;
    int m0   = blockIdx.x * 128;
    int m0w  = (wid >> 1) * 32;
    int n0w  = (wid & 1) * 40;

    int rA_loc = (lane & 7) + ((lane >> 3) & 1) * 8;
    uint32_t rowA0 = (uint32_t)((m0w + rA_loc) * 128);
    uint32_t rowA1 = rowA0 + 16 * 128;
    int rB_loc = (lane & 7) + ((lane >> 4) & 1) * 8;
    uint32_t rowB0 = (uint32_t)((n0w + rB_loc) * 128);
    uint32_t rowB1 = rowB0 + 16 * 128;
    uint32_t rowB2 = (uint32_t)((n0w + 32 + (lane & 7)) * 128);

    float acc[2][5][4];
    #pragma unroll
    for (int mt = 0; mt < 2; mt++)
        #pragma unroll
        for (int nt = 0; nt < 5; nt++)
            #pragma unroll
            for (int q = 0; q < 4; q++) acc[mt][nt][q] = 0.0f;

    load_stage(sb, m0, 0, tid);              CP_COMMIT();
    load_stage(sb + STG_BYTES, m0, KCH, tid); CP_COMMIT();

    for (int c = 0; c < NCH; c++) {
        if (c < NCH - 1) CP_WAIT1(); else CP_WAIT0();
        __syncthreads();

        uint32_t st  = sb + (uint32_t)((c & 1) * STG_BYTES);
        uint32_t sAH = st + OFF_AH, sAL = st + OFF_AL;
        uint32_t sBH = st + OFF_BH, sBL = st + OFF_BL;

        #pragma unroll
        for (int ks = 0; ks < 4; ks++) {
            uint32_t swA = (uint32_t)((((ks * 2) + (lane >> 4)) ^ (lane & 7)) * 16);
            uint32_t swB = (uint32_t)((((ks * 2) + ((lane >> 3) & 1)) ^ (lane & 7)) * 16);
            unsigned aH[2][4], aL[2][4], bH[10], bL[10];
            ldsm4(aH[0], sAH + rowA0 + swA);
            ldsm4(aH[1], sAH + rowA1 + swA);
            ldsm4(aL[0], sAL + rowA0 + swA);
            ldsm4(aL[1], sAL + rowA1 + swA);
            ldsm4(bH + 0, sBH + rowB0 + swB);
            ldsm4(bH + 4, sBH + rowB1 + swB);
            ldsm2(bH + 8, sBH + rowB2 + swB);
            ldsm4(bL + 0, sBL + rowB0 + swB);
            ldsm4(bL + 4, sBL + rowB1 + swB);
            ldsm2(bL + 8, sBL + rowB2 + swB);
            #pragma unroll
            for (int mt = 0; mt < 2; mt++)
                #pragma unroll
                for (int nt = 0; nt < 5; nt++) {
                    mma16816(acc[mt][nt], aH[mt], bH + 2 * nt);
                    mma16816(acc[mt][nt], aL[mt], bH + 2 * nt);
                    mma16816(acc[mt][nt], aH[mt], bL + 2 * nt);
                }
        }
        __syncthreads();
        if (c + 2 < NCH) { load_stage(sb + (uint32_t)((c & 1) * STG_BYTES), m0, (c + 2) * KCH, tid); CP_COMMIT(); }
    }

    // write accumulators to smem C[128][80]
    float* C = (float*)smem;
    int grp  = lane >> 2;
    int col0 = (lane & 3) * 2;
    #pragma unroll
    for (int mt = 0; mt < 2; mt++) {
        int r0 = m0w + mt * 16 + grp;
        #pragma unroll
        for (int nt = 0; nt < 5; nt++) {
            int cc = n0w + nt * 8 + col0;
            *(float2*)&C[r0 * 80 + cc]       = make_float2(acc[mt][nt][0], acc[mt][nt][1]);
            *(float2*)&C[(r0 + 8) * 80 + cc] = make_float2(acc[mt][nt][2], acc[mt][nt][3]);
        }
    }
    __syncthreads();

    #pragma unroll
    for (int u = tid; u < 2560; u += 256) {
        int al = u / 80, o = u % 80;
        int a = (m0 >> 2) + al;
        if (a < n_atoms) {
            float s0 = C[(al * 4 + 0) * 80 + o];
            float x  = C[(al * 4 + 1) * 80 + o];
            float y  = C[(al * 4 + 2) * 80 + o];
            float z  = C[(al * 4 + 3) * 80 + o];
            out[a * 80 + o] = s0 + selfb[o]
                + vecs[o] * sqrtf(fmaf(x, x, fmaf(y, y, z * z)) + 1e-30f);
        }
    }
}

// ---------------- launch ----------------
extern "C" void kernel_launch(void* const* d_in, const int* in_sizes, int n_in,
                              void* d_out, int out_size) {
    const float* feat  = (const float*)d_in[0];
    const float* dist  = (const float*)d_in[1];
    const float* coord = (const float*)d_in[2];
    const float* iw    = (const float*)d_in[3];
    const float* selfw = (const float*)d_in[4];
    const float* selfb = (const float*)d_in[5];
    const float* vecs  = (const float*)d_in[6];
    const float* mu    = (const float*)d_in[7];
    const float* sigma = (const float*)d_in[8];
    const int*   pf    = (const int*)d_in[9];
    const int*   ps    = (const int*)d_in[10];
    int n_pairs = in_sizes[9];
    int n_atoms = in_sizes[0] / 80;
    float* out = (float*)d_out;

    static int smem_set = 0;
    if (!smem_set) {
        cudaFuncSetAttribute(gemm_kernel, cudaFuncAttributeMaxDynamicSharedMemorySize,
                             2 * STG_BYTES);
        smem_set = 1;
    }

    build_w_kernel<<<(80 * KTOT + 255) / 256, 256>>>(iw, selfw);
    seg_kernel<<<(n_atoms + 256) / 256, 256>>>(pf, n_pairs, n_atoms);
    envsum_kernel<<<n_atoms / ATOMS_PER_BLK, 320>>>(feat, dist, coord, mu, sigma, ps);
    int mtiles = (n_atoms * 4 + 127) / 128;
    gemm_kernel<<<mtiles, 256, 2 * STG_BYTES>>>(selfb, vecs, out, n_atoms);
}